// round 9
// baseline (speedup 1.0000x reference)
#include <cuda_runtime.h>
#include <cuda_bf16.h>

#define CH 96
#define HH 128
#define WW 128
#define BC 1536
#define NF 129

// digit-reversed base-4 position (involution: P16(P16(k)) == k)
#define P16(k) ((((k) & 3) << 2) | ((k) >> 2))

__device__ float2 g_Kf[CH * NF * 256];       // full 2D FFT of k  [c][f][m]

#define TILE_N 16512                         // 128 rows * 129 bins
#define TP     129                           // tile pitch (odd -> conflict-free cols)
#define SCRP   272                           // per-group scratch (17-float pitch)
#define FUSED_GROUPS 64
#define PREP_GROUPS  32
#define FUSED_SMEM ((2*TILE_N + FUSED_GROUPS*SCRP) * 4)   // 201728 B
#define PREP_SMEM  ((2*TILE_N + PREP_GROUPS*SCRP) * 4)    // 166912 B

// ---------------------------------------------------------------------------
template<int SGN>
__device__ __forceinline__ void fft4(float& r0, float& i0, float& r1, float& i1,
                                     float& r2, float& i2, float& r3, float& i3) {
    float t0r = r0 + r2, t0i = i0 + i2, t1r = r0 - r2, t1i = i0 - i2;
    float t2r = r1 + r3, t2i = i1 + i3, t3r = r1 - r3, t3i = i1 - i3;
    float w3r = (SGN < 0) ? t3i : -t3i;
    float w3i = (SGN < 0) ? -t3r : t3r;
    r0 = t0r + t2r; i0 = t0i + t2i;
    r2 = t0r - t2r; i2 = t0i - t2i;
    r1 = t1r + w3r; i1 = t1i + w3i;
    r3 = t1r - w3r; i3 = t1i - w3i;
}

// In-register 16-point DFT. PIN=false: natural input, X[k] lands at P16(k).
// PIN=true: input stored in P16 layout, output lands in natural order.
template<int SGN, bool PIN>
__device__ __forceinline__ void fft16(float* r, float* im) {
#define IXQ(n) (PIN ? ((((n) & 3) << 2) | (((n) >> 2) & 3)) : (n))
    #pragma unroll
    for (int b = 0; b < 4; b++)
        fft4<SGN>(r[IXQ(b)], im[IXQ(b)], r[IXQ(b+4)], im[IXQ(b+4)],
                  r[IXQ(b+8)], im[IXQ(b+8)], r[IXQ(b+12)], im[IXQ(b+12)]);
    const float TC[10] = {1.f, 0.92387953f, 0.70710678f, 0.38268343f, 0.f,
                          0.f, -0.70710678f, 0.f, 0.f, -0.92387953f};
    const float TS[10] = {0.f, 0.38268343f, 0.70710678f, 0.92387953f, 1.f,
                          0.f, 0.70710678f, 0.f, 0.f, -0.38268343f};
    #pragma unroll
    for (int k1 = 1; k1 < 4; k1++)
        #pragma unroll
        for (int b = 1; b < 4; b++) {
            const int m = k1 * b, p = IXQ(4*k1 + b);
            const float c = TC[m], s = (float)SGN * TS[m];
            float vr = r[p] * c - im[p] * s;
            im[p]    = r[p] * s + im[p] * c;
            r[p]     = vr;
        }
    #pragma unroll
    for (int k1 = 0; k1 < 4; k1++)
        fft4<SGN>(r[IXQ(4*k1)], im[IXQ(4*k1)], r[IXQ(4*k1+1)], im[IXQ(4*k1+1)],
                  r[IXQ(4*k1+2)], im[IXQ(4*k1+2)], r[IXQ(4*k1+3)], im[IXQ(4*k1+3)]);
#undef IXQ
}

// 256-pt FFT by one 16-thread group, single scratch buffer (sequential r/i
// transpose passes). Thread j enters with z[16*n1+j] (natural if !PIN, P16
// layout if PIN); exits with X[16*k2+j] at position P16(k2).
template<int SGN, bool PIN>
__device__ __forceinline__ void fft256s(float* zr, float* zi, float* sc, int j) {
    fft16<SGN, PIN>(zr, zi);
    float wjs, wjc;
    __sincosf((float)SGN * (6.2831853071795864f / 256.f) * (float)j, &wjs, &wjc);
    float wr = 1.f, wi = 0.f;
    float ui[16];
    #pragma unroll
    for (int k1 = 0; k1 < 16; k1++) {
        const int p = PIN ? k1 : P16(k1);       // X[k1] position after fft16
        sc[k1 * 17 + j] = zr[p] * wr - zi[p] * wi;
        ui[k1]          = zr[p] * wi + zi[p] * wr;
        float nr = wr * wjc - wi * wjs;
        wi = wr * wjs + wi * wjc; wr = nr;
    }
    __syncwarp();
    float ar[16];
    #pragma unroll
    for (int n2 = 0; n2 < 16; n2++) ar[n2] = sc[j * 17 + n2];
    __syncwarp();
    #pragma unroll
    for (int k1 = 0; k1 < 16; k1++) sc[k1 * 17 + j] = ui[k1];
    __syncwarp();
    #pragma unroll
    for (int n2 = 0; n2 < 16; n2++) { zr[n2] = ar[n2]; zi[n2] = sc[j * 17 + n2]; }
    __syncwarp();
    fft16<SGN, false>(zr, zi);
}

// Unpack a packed-real forward FFT (Z of A+iB) into the two hermitian halves
// and write bins 0..128 of rows baseA/baseB into the tile. All groups execute
// uniformly (full-mask shfl, width 16).
__device__ __forceinline__ void unpack_rows_to_tile(
    const float* zr, const float* zi, float* tr, float* ti,
    int baseA, int baseB, int j) {
    #pragma unroll
    for (int k2 = 0; k2 < 8; k2++) {
        float sr_ = zr[P16(15 - k2)], si_ = zi[P16(15 - k2)];
        float mr_ = __shfl_sync(0xffffffffu, sr_, (16 - j) & 15, 16);
        float mi_ = __shfl_sync(0xffffffffu, si_, (16 - j) & 15, 16);
        if (j == 0) { mr_ = zr[P16((16 - k2) & 15)]; mi_ = zi[P16((16 - k2) & 15)]; }
        const float zkr = zr[P16(k2)], zki = zi[P16(k2)];
        tr[baseA + k2*16 + j] = 0.5f * (zkr + mr_);
        ti[baseA + k2*16 + j] = 0.5f * (zki - mi_);
        tr[baseB + k2*16 + j] = 0.5f * (zki + mi_);
        ti[baseB + k2*16 + j] = 0.5f * (mr_ - zkr);
    }
    if (j == 0) {                              // bin 128 (self-mirror, real)
        tr[baseA + 128] = zr[P16(8)];  ti[baseA + 128] = 0.f;
        tr[baseB + 128] = zi[P16(8)];  ti[baseB + 128] = 0.f;
    }
}

// ---------------------------------------------------------------------------
// kprep: one block per channel. MLP + row rFFT (packed pairs) -> tile,
// then column FFTs -> g_Kf (columns 0 and 128 packed as one complex FFT).
// ---------------------------------------------------------------------------
__global__ void __launch_bounds__(512)
kprep_kernel(const float* __restrict__ W1, const float* __restrict__ b1,
             const float* __restrict__ W2, const float* __restrict__ b2) {
    extern __shared__ float smem[];
    float* tr  = smem;
    float* ti  = smem + TILE_N;
    float* scr = smem + 2*TILE_N;
    const int t = threadIdx.x, g = t >> 4, j = t & 15;
    const int c = blockIdx.x;
    float* sc = scr + g * SCRP;

    float w1a[16], w1b[16], bb1[16], w2[16];
    #pragma unroll
    for (int h = 0; h < 16; h++) {
        w1a[h] = W1[h]; w1b[h] = W1[16 + h]; bb1[h] = b1[h]; w2[h] = W2[h * CH + c];
    }
    const float bias = b2[c];

    // Phase 1: 64 packed row FFTs (rows r, r+64), 2 iters of 32 groups
    #pragma unroll 1
    for (int it = 0; it < 2; it++) {
        const int rA = it * 32 + g, rB = rA + 64;
        const float gyA = (float)rA * (1.f / 127.f);
        const float gyB = (float)rB * (1.f / 127.f);
        float zr[16], zi[16];
        #pragma unroll
        for (int n1 = 0; n1 < 16; n1++) {
            const int col = n1 * 16 + j;
            float vA = 0.f, vB = 0.f;
            if (col < 128) {
                const float gx = (float)col * (1.f / 127.f);
                vA = bias; vB = bias;
                #pragma unroll
                for (int h = 0; h < 16; h++) {
                    const float gxw = gx * w1b[h] + bb1[h];
                    vA += fmaxf(gyA * w1a[h] + gxw, 0.f) * w2[h];
                    vB += fmaxf(gyB * w1a[h] + gxw, 0.f) * w2[h];
                }
            }
            zr[n1] = vA; zi[n1] = vB;
        }
        fft256s<-1, false>(zr, zi, sc, j);
        unpack_rows_to_tile(zr, zi, tr, ti, rA * TP, rB * TP, j);
    }
    __syncthreads();

    // Phase 2: 128 column tasks (task 0 = packed cols 0&128), 4 iters
    #pragma unroll 1
    for (int it = 0; it < 4; it++) {
        const int f = it * 32 + g;
        float zr[16], zi[16];
        #pragma unroll
        for (int n1 = 0; n1 < 16; n1++) {
            const int row = n1 * 16 + j;
            if (row < 128) {
                if (f == 0) { zr[n1] = tr[row * TP];     zi[n1] = tr[row * TP + 128]; }
                else        { zr[n1] = tr[row * TP + f]; zi[n1] = ti[row * TP + f]; }
            } else { zr[n1] = 0.f; zi[n1] = 0.f; }
        }
        fft256s<-1, false>(zr, zi, sc, j);
        if (f == 0) {
            // unpack the two hermitian spectra, store Kf cols 0 and 128
            #pragma unroll
            for (int k2 = 0; k2 < 16; k2++) {
                const int p = P16(k2);
                float sr_ = zr[P16(15 - k2)], si_ = zi[P16(15 - k2)];
                float mr_ = __shfl_sync(0xffffu, sr_, (16 - j) & 15, 16);
                float mi_ = __shfl_sync(0xffffu, si_, (16 - j) & 15, 16);
                if (j == 0) { mr_ = zr[P16((16 - k2) & 15)]; mi_ = zi[P16((16 - k2) & 15)]; }
                const float Ar = 0.5f * (zr[p] + mr_), Ai = 0.5f * (zi[p] - mi_);
                const float Br = 0.5f * (zi[p] + mi_), Bi = 0.5f * (mr_ - zr[p]);
                g_Kf[(c * NF +   0) * 256 + k2*16 + j] = make_float2(Ar, Ai);
                g_Kf[(c * NF + 128) * 256 + k2*16 + j] = make_float2(Br, Bi);
            }
        } else {
            const int kb = (c * NF + f) * 256;
            #pragma unroll
            for (int k2 = 0; k2 < 16; k2++)
                g_Kf[kb + k2*16 + j] = make_float2(zr[P16(k2)], zi[P16(k2)]);
        }
    }
}

// ---------------------------------------------------------------------------
// Fused per-image kernel: 1024 threads = 64 groups. One block = one image.
// ---------------------------------------------------------------------------
__global__ void __launch_bounds__(1024, 1)
fused_kernel(const float* __restrict__ x, float* __restrict__ out) {
    extern __shared__ float smem[];
    float* tr  = smem;
    float* ti  = smem + TILE_N;
    float* scr = smem + 2*TILE_N;
    const int t = threadIdx.x, g = t >> 4, j = t & 15;
    const int bc = blockIdx.x;
    const int c  = bc % CH;
    float* sc = scr + g * SCRP;

    // ---- Phase 1: 64 packed row rFFTs, exactly one pass ----
    {
        const int rA = g, rB = g + 64;
        const int xa = (bc * HH + rA) * WW;
        const int xb = (bc * HH + rB) * WW;
        float zr[16], zi[16];
        #pragma unroll
        for (int n1 = 0; n1 < 16; n1++) {
            const int col = n1 * 16 + j;
            if (col < 128) { zr[n1] = x[xa + col]; zi[n1] = x[xb + col]; }
            else           { zr[n1] = 0.f;         zi[n1] = 0.f; }
        }
        fft256s<-1, false>(zr, zi, sc, j);
        unpack_rows_to_tile(zr, zi, tr, ti, rA * TP, rB * TP, j);
    }
    __syncthreads();

    // ---- Phase 2: 128 column tasks (task 0 = packed cols 0&128), 2 passes ----
    #pragma unroll 1
    for (int it = 0; it < 2; it++) {
        const int f = it * 64 + g;
        float zr[16], zi[16];
        #pragma unroll
        for (int n1 = 0; n1 < 16; n1++) {
            const int row = n1 * 16 + j;
            if (row < 128) {
                if (f == 0) { zr[n1] = tr[row * TP];     zi[n1] = tr[row * TP + 128]; }
                else        { zr[n1] = tr[row * TP + f]; zi[n1] = ti[row * TP + f]; }
            } else { zr[n1] = 0.f; zi[n1] = 0.f; }
        }
        fft256s<-1, false>(zr, zi, sc, j);      // forward along column

        if (f == 0) {
            // snapshot (mirror reads must see pre-multiply values)
            float or_[16], oi_[16];
            #pragma unroll
            for (int q = 0; q < 16; q++) { or_[q] = zr[q]; oi_[q] = zi[q]; }
            #pragma unroll
            for (int k2 = 0; k2 < 16; k2++) {
                const int p = P16(k2);
                float mr_ = __shfl_sync(0xffffu, or_[P16(15 - k2)], (16 - j) & 15, 16);
                float mi_ = __shfl_sync(0xffffu, oi_[P16(15 - k2)], (16 - j) & 15, 16);
                if (j == 0) { mr_ = or_[P16((16 - k2) & 15)]; mi_ = oi_[P16((16 - k2) & 15)]; }
                const float Ar = 0.5f * (or_[p] + mr_), Ai = 0.5f * (oi_[p] - mi_);
                const float Br = 0.5f * (oi_[p] + mi_), Bi = 0.5f * (mr_ - or_[p]);
                const float2 k0 = g_Kf[(c * NF +   0) * 256 + k2*16 + j];
                const float2 kn = g_Kf[(c * NF + 128) * 256 + k2*16 + j];
                const float Cr = Ar * k0.x - Ai * k0.y, Ci = Ar * k0.y + Ai * k0.x;
                const float Dr = Br * kn.x - Bi * kn.y, Di = Br * kn.y + Bi * kn.x;
                zr[p] = Cr - Di;                 // repack: Y = C + i*D
                zi[p] = Ci + Dr;
            }
        } else {
            const int kb = (c * NF + f) * 256;
            #pragma unroll
            for (int k2 = 0; k2 < 16; k2++) {
                const float2 kv = g_Kf[kb + k2*16 + j];
                const int p = P16(k2);
                const float a = zr[p], b = zi[p];
                zr[p] = a * kv.x - b * kv.y;
                zi[p] = a * kv.y + b * kv.x;
            }
        }
        fft256s<1, true>(zr, zi, sc, j);        // unnormalized inverse (PIN input)
        if (f == 0) {
            #pragma unroll
            for (int k2 = 0; k2 < 8; k2++) {     // keep rows 0..127; cols real
                const int row = k2 * 16 + j;
                tr[row * TP]       = zr[P16(k2)];  ti[row * TP]       = 0.f;
                tr[row * TP + 128] = zi[P16(k2)];  ti[row * TP + 128] = 0.f;
            }
        } else {
            #pragma unroll
            for (int k2 = 0; k2 < 8; k2++) {
                const int row = k2 * 16 + j;
                tr[row * TP + f] = zr[P16(k2)];
                ti[row * TP + f] = zi[P16(k2)];
            }
        }
    }
    __syncthreads();

    // ---- Phase 3: 64 packed hermitian row inverses + residual, one pass ----
    {
        const int rA = g, rB = g + 64;
        const int baseA = rA * TP, baseB = rB * TP;
        float zr[16], zi[16];
        #pragma unroll
        for (int n1 = 0; n1 < 16; n1++) {
            const int n = n1 * 16 + j;
            float Ar, Ai, Br, Bi;
            if (n <= 128) {
                Ar = tr[baseA + n]; Ai = ti[baseA + n];
                Br = tr[baseB + n]; Bi = ti[baseB + n];
            } else {
                const int m2 = 256 - n;           // hermitian mirror
                Ar = tr[baseA + m2]; Ai = -ti[baseA + m2];
                Br = tr[baseB + m2]; Bi = -ti[baseB + m2];
            }
            zr[n1] = Ar - Bi;                     // Z = A + i*B
            zi[n1] = Ai + Br;
        }
        fft256s<1, false>(zr, zi, sc, j);         // z[n] = a[n] + i*b[n]
        const int ga = (bc * HH + rA) * WW;
        const int gb = (bc * HH + rB) * WW;
        #pragma unroll
        for (int k2 = 0; k2 < 8; k2++) {
            const int col = k2 * 16 + j;
            out[ga + col] = zr[P16(k2)] + x[ga + col];
            out[gb + col] = zi[P16(k2)] + x[gb + col];
        }
    }
}

// ---------------------------------------------------------------------------
extern "C" void kernel_launch(void* const* d_in, const int* in_sizes, int n_in,
                              void* d_out, int out_size) {
    const float* x  = (const float*)d_in[0];
    const float* W1 = (const float*)d_in[1];
    const float* b1 = (const float*)d_in[2];
    const float* W2 = (const float*)d_in[3];
    const float* b2 = (const float*)d_in[4];
    float* out = (float*)d_out;

    static int smem_set = 0;
    if (!smem_set) {
        cudaFuncSetAttribute(kprep_kernel,
                             cudaFuncAttributeMaxDynamicSharedMemorySize, PREP_SMEM);
        cudaFuncSetAttribute(fused_kernel,
                             cudaFuncAttributeMaxDynamicSharedMemorySize, FUSED_SMEM);
        smem_set = 1;
    }

    kprep_kernel<<<CH, 512, PREP_SMEM>>>(W1, b1, W2, b2);
    fused_kernel<<<BC, 1024, FUSED_SMEM>>>(x, out);
}